// round 4
// baseline (speedup 1.0000x reference)
#include <cuda_runtime.h>
#include <cuda_bf16.h>
#include <cstdint>

#define N_NODES   20000
#define N_EDGES   320000
#define NUM_HEADS 8
#define NEG_SLOPE 0.2f

// ---------------- device scratch ----------------
__device__ float g_node_tbl[N_NODES * 640];   // [0:256)=ni_h, [256:512)=nj_h, [512:640)=node part of msg
__device__ float g_ex[N_EDGES * NUM_HEADS];
__device__ float g_msg[N_EDGES * 128];
__device__ float g_node_sum[N_NODES * NUM_HEADS];
__device__ float g_agg[N_NODES * 128];
// prepacked weights (bf16 hi/lo splits, [n][k] k-contiguous == col-major B for mma)
__device__ __nv_bfloat16 g_WNh[640 * 128];
__device__ __nv_bfloat16 g_WNl[640 * 128];
__device__ __nv_bfloat16 g_WEh[384 * 128];
__device__ __nv_bfloat16 g_WEl[384 * 128];
__device__ float g_bN[640];
__device__ float g_bE[384];
__device__ float g_WO[128 * 128];             // [k][n] for FFMA out gemm

// ---------------- helpers ----------------
__device__ __forceinline__ uint32_t smem_u32(const void* p) {
    uint32_t a;
    asm("{ .reg .u64 t; cvta.to.shared.u64 t, %1; cvt.u32.u64 %0, t; }" : "=r"(a) : "l"(p));
    return a;
}

#define LDSM_X4(r0, r1, r2, r3, addr) \
    asm volatile("ldmatrix.sync.aligned.m8n8.x4.shared.b16 {%0,%1,%2,%3}, [%4];" \
                 : "=r"(r0), "=r"(r1), "=r"(r2), "=r"(r3) : "r"(addr))

#define MMA_BF16(c, a, b) \
    asm volatile("mma.sync.aligned.m16n8k16.row.col.f32.bf16.bf16.f32 " \
                 "{%0,%1,%2,%3}, {%4,%5,%6,%7}, {%8,%9}, {%0,%1,%2,%3};" \
                 : "+f"((c)[0]), "+f"((c)[1]), "+f"((c)[2]), "+f"((c)[3]) \
                 : "r"((a)[0]), "r"((a)[1]), "r"((a)[2]), "r"((a)[3]), \
                   "r"((b)[0]), "r"((b)[1]))

// smem layout (bytes). bf16 tiles have row pitch 136 elems (272 B) for ldmatrix
// conflict-freedom; f32 C staging has pitch 132 floats.
#define APITCH_B 272
#define SM_AH 0
#define SM_AL 34816
#define SM_BH 69632
#define SM_BL 104448
#define SM_TOT 139264
#define SM_C  0              // reuses Ah/Al region after sync
#define CPITCH 132

// ---------------- init kernels ----------------
__global__ void zero_kernel() {
    int i = blockIdx.x * blockDim.x + threadIdx.x;
    const int NS = N_NODES * NUM_HEADS;
    const int TOT = NS + N_NODES * 128;
    if (i < NS) g_node_sum[i] = 0.f;
    else if (i < TOT) g_agg[i - NS] = 0.f;
}

__device__ __forceinline__ void split_store(float v, __nv_bfloat16* hi, __nv_bfloat16* lo, int i) {
    __nv_bfloat16 h = __float2bfloat16(v);
    hi[i] = h;
    lo[i] = __float2bfloat16(v - __bfloat162float(h));
}

__global__ void prepack_kernel(const float* __restrict__ Wni, const float* __restrict__ bni,
                               const float* __restrict__ Wnj, const float* __restrict__ bnj,
                               const float* __restrict__ We,  const float* __restrict__ be,
                               const float* __restrict__ Wm,  const float* __restrict__ bm,
                               const float* __restrict__ Wo) {
    int i = blockIdx.x * blockDim.x + threadIdx.x;
    if (i < 81920) {                       // WN [640][128]
        int n = i >> 7, k = i & 127;
        float v;
        if (n < 256)      v = Wni[n * 128 + k];
        else if (n < 512) v = Wnj[(n - 256) * 128 + k];
        else              v = Wm[(n - 512) * 256 + k];
        split_store(v, g_WNh, g_WNl, i);
    }
    if (i < 49152) {                       // WE [384][128]
        int n = i >> 7, k = i & 127;
        float v = (n < 256) ? We[n * 128 + k] : Wm[(n - 256) * 256 + 128 + k];
        split_store(v, g_WEh, g_WEl, i);
    }
    if (i < 640) g_bN[i] = (i < 256) ? bni[i] : (i < 512 ? bnj[i - 256] : 0.f);
    if (i < 384) g_bE[i] = (i < 256) ? be[i] : bm[i - 256];
    if (i < 16384) {                       // WO [k][n]
        int k = i >> 7, n = i & 127;
        g_WO[i] = Wo[n * 128 + k];
    }
}

// ---------------- HMMA split-bf16 GEMM + fused epilogues ----------------
// C_tile[128x128] = A[m0:m0+128, 0:128] @ B[n0:n0+128, 0:128]^T  (3-term bf16 split)
// mode 0: node tables -> g_node_tbl (+bias)
// mode 1: edge pass; nt 0,1 -> attention hidden epilogue; nt 2 -> message epilogue
__global__ void __launch_bounds__(256, 1) mma_kernel(
    int mode, const float* __restrict__ A, int M,
    const int* __restrict__ EI, const float* __restrict__ AP) {
    extern __shared__ char smem[];
    uint32_t sb = smem_u32(smem);
    int tid = threadIdx.x;
    int wid = tid >> 5, lid = tid & 31;
    int m0 = blockIdx.x * 128;
    int nt = blockIdx.y;
    int n0 = nt * 128;

    // ---- fill A tile: f32 -> hi/lo bf16, row pitch 136 ----
    for (int u = tid; u < 4096; u += 256) {
        int r = u >> 5, c = (u & 31) << 2;
        int row = m0 + r;
        float4 v = make_float4(0.f, 0.f, 0.f, 0.f);
        if (row < M) v = *(const float4*)(A + (size_t)row * 128 + c);
        __nv_bfloat162 h01 = __floats2bfloat162_rn(v.x, v.y);
        __nv_bfloat162 h23 = __floats2bfloat162_rn(v.z, v.w);
        float2 f01 = __bfloat1622float2(h01);
        float2 f23 = __bfloat1622float2(h23);
        __nv_bfloat162 l01 = __floats2bfloat162_rn(v.x - f01.x, v.y - f01.y);
        __nv_bfloat162 l23 = __floats2bfloat162_rn(v.z - f23.x, v.w - f23.y);
        uint32_t off = r * APITCH_B + c * 2;
        *(uint2*)(smem + SM_AH + off) = make_uint2(*(uint32_t*)&h01, *(uint32_t*)&h23);
        *(uint2*)(smem + SM_AL + off) = make_uint2(*(uint32_t*)&l01, *(uint32_t*)&l23);
    }
    // ---- fill B tile from prepacked bf16 [n][k] ----
    const __nv_bfloat16* Bh = (mode == 0) ? g_WNh : g_WEh;
    const __nv_bfloat16* Bl = (mode == 0) ? g_WNl : g_WEl;
    for (int u = tid; u < 2048; u += 256) {
        int r = u >> 4, c = (u & 15) << 3;
        uint32_t off = r * APITCH_B + c * 2;
        *(uint4*)(smem + SM_BH + off) = *(const uint4*)(Bh + (size_t)(n0 + r) * 128 + c);
        *(uint4*)(smem + SM_BL + off) = *(const uint4*)(Bl + (size_t)(n0 + r) * 128 + c);
    }
    __syncthreads();

    // warp tile: rows wm*32 .. +32, cols wn*64 .. +64
    int wm = wid & 3, wn = wid >> 2;
    float acc[2][8][4];
#pragma unroll
    for (int i = 0; i < 2; i++)
#pragma unroll
        for (int f = 0; f < 8; f++)
#pragma unroll
            for (int j = 0; j < 4; j++) acc[i][f][j] = 0.f;

    int lr = lid & 15, lc = lid >> 4;   // ldmatrix address lanes
#pragma unroll
    for (int ks = 0; ks < 8; ks++) {
        int kc = ks * 16;
        uint32_t ah[2][4], al[2][4], bhf[8][2], blf[8][2];
#pragma unroll
        for (int mf = 0; mf < 2; mf++) {
            uint32_t aoff = (uint32_t)((wm * 32 + mf * 16 + lr) * APITCH_B + (kc + lc * 8) * 2);
            LDSM_X4(ah[mf][0], ah[mf][1], ah[mf][2], ah[mf][3], sb + SM_AH + aoff);
            LDSM_X4(al[mf][0], al[mf][1], al[mf][2], al[mf][3], sb + SM_AL + aoff);
        }
#pragma unroll
        for (int g = 0; g < 4; g++) {
            uint32_t boff = (uint32_t)((wn * 64 + g * 16 + lr) * APITCH_B + (kc + lc * 8) * 2);
            uint32_t t0, t1, t2, t3;
            LDSM_X4(t0, t1, t2, t3, sb + SM_BH + boff);
            bhf[2 * g][0] = t0; bhf[2 * g][1] = t2;
            bhf[2 * g + 1][0] = t1; bhf[2 * g + 1][1] = t3;
            LDSM_X4(t0, t1, t2, t3, sb + SM_BL + boff);
            blf[2 * g][0] = t0; blf[2 * g][1] = t2;
            blf[2 * g + 1][0] = t1; blf[2 * g + 1][1] = t3;
        }
#pragma unroll
        for (int mf = 0; mf < 2; mf++)
#pragma unroll
            for (int f = 0; f < 8; f++) {
                MMA_BF16(acc[mf][f], ah[mf], bhf[f]);
                MMA_BF16(acc[mf][f], ah[mf], blf[f]);
                MMA_BF16(acc[mf][f], al[mf], bhf[f]);
            }
    }

    // ---- stage C through smem (reuses A region) ----
    __syncthreads();
    float* Cs = (float*)(smem + SM_C);
#pragma unroll
    for (int mf = 0; mf < 2; mf++)
#pragma unroll
        for (int f = 0; f < 8; f++) {
            int r0 = wm * 32 + mf * 16 + (lid >> 2);
            int cc = wn * 64 + f * 8 + (lid & 3) * 2;
            *(float2*)(Cs + r0 * CPITCH + cc)       = make_float2(acc[mf][f][0], acc[mf][f][1]);
            *(float2*)(Cs + (r0 + 8) * CPITCH + cc) = make_float2(acc[mf][f][2], acc[mf][f][3]);
        }
    __syncthreads();

    // ---- row-linear epilogue: thread t -> row t>>1, col half t&1 (64 cols) ----
    int r = tid >> 1, h = tid & 1;
    int row = m0 + r;
    const float* crow = Cs + r * CPITCH + h * 64;

    if (mode == 0) {
        if (row < M) {
            float* dst = g_node_tbl + (size_t)row * 640 + n0 + h * 64;
            const float* bi = g_bN + n0 + h * 64;
#pragma unroll
            for (int j = 0; j < 64; j += 4) {
                float4 c4 = *(const float4*)(crow + j);
                float4 o;
                o.x = c4.x + bi[j + 0];
                o.y = c4.y + bi[j + 1];
                o.z = c4.z + bi[j + 2];
                o.w = c4.w + bi[j + 3];
                *(float4*)(dst + j) = o;
            }
        }
    } else if (nt < 2) {
        int e = row;
        int s = EI[e], dn = EI[N_EDGES + e];
#pragma unroll
        for (int hd = 0; hd < 2; hd++) {
            int head = nt * 4 + h * 2 + hd;
            int cg = h * 64 + hd * 32;                     // col within this 128-block
            const float* cc = crow + hd * 32;
            const float* bi = g_bE + nt * 128 + cg;
            const float* ap = AP + head * 32;
            const float* ni = g_node_tbl + (size_t)s  * 640 +       nt * 128 + cg;
            const float* nj = g_node_tbl + (size_t)dn * 640 + 256 + nt * 128 + cg;
            float p = 0.f;
#pragma unroll
            for (int j = 0; j < 32; j += 4) {
                float4 c4 = *(const float4*)(cc + j);
                float4 nv = *(const float4*)(ni + j);
                float4 jv = *(const float4*)(nj + j);
                float4 bv = *(const float4*)(bi + j);
                float4 av = *(const float4*)(ap + j);
                float hh;
                hh = c4.x + bv.x + nv.x + jv.x; hh = (hh >= 0.f) ? hh : NEG_SLOPE * hh; p += hh * av.x;
                hh = c4.y + bv.y + nv.y + jv.y; hh = (hh >= 0.f) ? hh : NEG_SLOPE * hh; p += hh * av.y;
                hh = c4.z + bv.z + nv.z + jv.z; hh = (hh >= 0.f) ? hh : NEG_SLOPE * hh; p += hh * av.z;
                hh = c4.w + bv.w + nv.w + jv.w; hh = (hh >= 0.f) ? hh : NEG_SLOPE * hh; p += hh * av.w;
            }
            float ex = expf(p);
            g_ex[e * 8 + head] = ex;
            atomicAdd(&g_node_sum[s * 8 + head], ex);
        }
    } else {
        int e = row;
        int dn = EI[N_EDGES + e];
        const float* nm = g_node_tbl + (size_t)dn * 640 + 512 + h * 64;
        const float* bi = g_bE + 256 + h * 64;
        float* dst = g_msg + (size_t)e * 128 + h * 64;
#pragma unroll
        for (int j = 0; j < 64; j += 4) {
            float4 c4 = *(const float4*)(crow + j);
            float4 o;
            o.x = c4.x + bi[j + 0] + nm[j + 0];
            o.y = c4.y + bi[j + 1] + nm[j + 1];
            o.z = c4.z + bi[j + 2] + nm[j + 2];
            o.w = c4.w + bi[j + 3] + nm[j + 3];
            *(float4*)(dst + j) = o;
        }
    }
}

// ---------------- softmax-weight + scatter-aggregate ----------------
__global__ void agg_kernel(const int* __restrict__ EI) {
    int e = (blockIdx.x * blockDim.x + threadIdx.x) >> 5;
    int lane = threadIdx.x & 31;
    if (e >= N_EDGES) return;
    int s = EI[e];
    int head = lane >> 2;
    float ex = g_ex[e * 8 + head];
    float sum = g_node_sum[s * 8 + head];
    float w = ex / sum;
    float4 m = *(const float4*)(g_msg + (size_t)e * 128 + lane * 4);
    float* dst = g_agg + (size_t)s * 128 + lane * 4;
    asm volatile("red.global.add.v4.f32 [%0], {%1,%2,%3,%4};"
                 :: "l"(dst), "f"(m.x * w), "f"(m.y * w), "f"(m.z * w), "f"(m.w * w)
                 : "memory");
}

// ---------------- FFMA GEMM for the small output projection ----------------
__global__ void gemm_kernel(const float* __restrict__ A, const float* __restrict__ B,
                            const float* __restrict__ bias, float* __restrict__ C,
                            int M, int N, int K) {
    __shared__ float As[16][64];
    __shared__ float Bs[16][64];
    int tid = threadIdx.x;
    int rt = tid >> 4, ct = tid & 15;
    int m0 = blockIdx.x * 64, n0 = blockIdx.y * 64;
    float acc[4][4] = {};
    int arow = tid >> 2, aq = tid & 3;
    int bk = tid >> 4, bq = tid & 15;
    for (int k0 = 0; k0 < K; k0 += 16) {
        float4 av = make_float4(0.f, 0.f, 0.f, 0.f);
        if (m0 + arow < M)
            av = *(const float4*)(A + (size_t)(m0 + arow) * K + k0 + aq * 4);
        As[aq * 4 + 0][arow] = av.x; As[aq * 4 + 1][arow] = av.y;
        As[aq * 4 + 2][arow] = av.z; As[aq * 4 + 3][arow] = av.w;
        float4 bv = *(const float4*)(B + (size_t)(k0 + bk) * N + n0 + bq * 4);
        *(float4*)&Bs[bk][bq * 4] = bv;
        __syncthreads();
#pragma unroll
        for (int kk = 0; kk < 16; kk++) {
            float a[4], b[4];
            *(float4*)a = *(float4*)&As[kk][rt * 4];
            *(float4*)b = *(float4*)&Bs[kk][ct * 4];
#pragma unroll
            for (int i = 0; i < 4; i++)
#pragma unroll
                for (int j = 0; j < 4; j++)
                    acc[i][j] += a[i] * b[j];
        }
        __syncthreads();
    }
#pragma unroll
    for (int i = 0; i < 4; i++) {
        int m = m0 + rt * 4 + i;
        if (m < M) {
            int n = n0 + ct * 4;
            float4 o;
            o.x = acc[i][0] + bias[n + 0];
            o.y = acc[i][1] + bias[n + 1];
            o.z = acc[i][2] + bias[n + 2];
            o.w = acc[i][3] + bias[n + 3];
            *(float4*)(C + (size_t)m * N + n) = o;
        }
    }
}

// ---------------- launch ----------------
extern "C" void kernel_launch(void* const* d_in, const int* in_sizes, int n_in,
                              void* d_out, int out_size) {
    const float* node_features = (const float*)d_in[0];
    const float* edge_features = (const float*)d_in[1];
    const int*   edge_index    = (const int*)d_in[2];
    const float* Wni = (const float*)d_in[3];
    const float* bni = (const float*)d_in[4];
    const float* Wnj = (const float*)d_in[5];
    const float* bnj = (const float*)d_in[6];
    const float* We  = (const float*)d_in[7];
    const float* be  = (const float*)d_in[8];
    const float* attn_proj = (const float*)d_in[9];
    const float* Wm  = (const float*)d_in[10];
    const float* bm  = (const float*)d_in[11];
    const float* Wo  = (const float*)d_in[12];
    const float* bo  = (const float*)d_in[13];
    float* out = (float*)d_out;

    float *pAgg, *pWO;
    cudaGetSymbolAddress((void**)&pAgg, g_agg);
    cudaGetSymbolAddress((void**)&pWO,  g_WO);

    static bool attr_set = false;
    if (!attr_set) {
        cudaFuncSetAttribute(mma_kernel, cudaFuncAttributeMaxDynamicSharedMemorySize, SM_TOT);
        attr_set = true;
    }

    const int ZTOT = N_NODES * NUM_HEADS + N_NODES * 128;
    zero_kernel<<<(ZTOT + 255) / 256, 256>>>();
    prepack_kernel<<<(81920 + 255) / 256, 256>>>(Wni, bni, Wnj, bnj, We, be, Wm, bm, Wo);

    // node tables: 157 M-tiles x 5 N-tiles of 128
    mma_kernel<<<dim3((N_NODES + 127) / 128, 5), 256, SM_TOT>>>(
        0, node_features, N_NODES, edge_index, attn_proj);

    // edge pass: 2500 M-tiles x 3 N-tiles
    mma_kernel<<<dim3(N_EDGES / 128, 3), 256, SM_TOT>>>(
        1, edge_features, N_EDGES, edge_index, attn_proj);

    // aggregate: one warp per edge
    agg_kernel<<<N_EDGES / 8, 256>>>(edge_index);

    // output projection
    gemm_kernel<<<dim3((N_NODES + 63) / 64, 2), 256>>>(pAgg, pWO, bo, out, N_NODES, 128, 128);
}

// round 6
// speedup vs baseline: 1.1985x; 1.1985x over previous
#include <cuda_runtime.h>
#include <cuda_bf16.h>
#include <cstdint>

#define N_NODES   20000
#define N_EDGES   320000
#define NUM_HEADS 8
#define NEG_SLOPE 0.2f

// ---------------- device scratch ----------------
__device__ float g_node_tbl[N_NODES * 640];   // [0:256)=ni_h, [256:512)=nj_h, [512:640)=node part of msg
__device__ float g_ex[N_EDGES * NUM_HEADS];
__device__ float g_msg[N_EDGES * 128];
__device__ float g_node_sum[N_NODES * NUM_HEADS];
__device__ float g_agg[N_NODES * 128];
// prepacked weights (bf16 hi/lo splits, [n][k] k-contiguous == col-major B for mma)
__device__ __nv_bfloat16 g_WNh[640 * 128];
__device__ __nv_bfloat16 g_WNl[640 * 128];
__device__ __nv_bfloat16 g_WEh[384 * 128];
__device__ __nv_bfloat16 g_WEl[384 * 128];
__device__ float g_bN[640];
__device__ float g_bE[384];
__device__ float g_WO[128 * 128];             // [k][n] for FFMA out gemm

// ---------------- helpers ----------------
__device__ __forceinline__ uint32_t smem_u32(const void* p) {
    uint32_t a;
    asm("{ .reg .u64 t; cvta.to.shared.u64 t, %1; cvt.u32.u64 %0, t; }" : "=r"(a) : "l"(p));
    return a;
}

#define LDSM_X4(r0, r1, r2, r3, addr) \
    asm volatile("ldmatrix.sync.aligned.m8n8.x4.shared.b16 {%0,%1,%2,%3}, [%4];" \
                 : "=r"(r0), "=r"(r1), "=r"(r2), "=r"(r3) : "r"(addr))

#define MMA_BF16(c, a, b) \
    asm volatile("mma.sync.aligned.m16n8k16.row.col.f32.bf16.bf16.f32 " \
                 "{%0,%1,%2,%3}, {%4,%5,%6,%7}, {%8,%9}, {%0,%1,%2,%3};" \
                 : "+f"((c)[0]), "+f"((c)[1]), "+f"((c)[2]), "+f"((c)[3]) \
                 : "r"((a)[0]), "r"((a)[1]), "r"((a)[2]), "r"((a)[3]), \
                   "r"((b)[0]), "r"((b)[1]))

// smem layout (bytes): A hi/lo (pitch 272B), B hi/lo (pitch 272B), C f32 staging
#define APITCH_B 272
#define SM_AH 0
#define SM_AL 34816
#define SM_BH 69632
#define SM_BL 104448
#define SM_C  139264
#define CPITCH 132                        // 132 mod 32 = 4 -> conflict-free row-major reads
#define SM_TOT (139264 + 128 * CPITCH * 4)   // 206848

// ---------------- init kernels ----------------
__global__ void zero_kernel() {
    int i = blockIdx.x * blockDim.x + threadIdx.x;
    const int NS = N_NODES * NUM_HEADS;
    const int TOT = NS + N_NODES * 128;
    if (i < NS) g_node_sum[i] = 0.f;
    else if (i < TOT) g_agg[i - NS] = 0.f;
}

__device__ __forceinline__ void split_store(float v, __nv_bfloat16* hi, __nv_bfloat16* lo, int i) {
    __nv_bfloat16 h = __float2bfloat16(v);
    hi[i] = h;
    lo[i] = __float2bfloat16(v - __bfloat162float(h));
}

__global__ void prepack_kernel(const float* __restrict__ Wni, const float* __restrict__ bni,
                               const float* __restrict__ Wnj, const float* __restrict__ bnj,
                               const float* __restrict__ We,  const float* __restrict__ be,
                               const float* __restrict__ Wm,  const float* __restrict__ bm,
                               const float* __restrict__ Wo) {
    int i = blockIdx.x * blockDim.x + threadIdx.x;
    if (i < 81920) {                       // WN [640][128]
        int n = i >> 7, k = i & 127;
        float v;
        if (n < 256)      v = Wni[n * 128 + k];
        else if (n < 512) v = Wnj[(n - 256) * 128 + k];
        else              v = Wm[(n - 512) * 256 + k];
        split_store(v, g_WNh, g_WNl, i);
    }
    if (i < 49152) {                       // WE [384][128]
        int n = i >> 7, k = i & 127;
        float v = (n < 256) ? We[n * 128 + k] : Wm[(n - 256) * 256 + 128 + k];
        split_store(v, g_WEh, g_WEl, i);
    }
    if (i < 640) g_bN[i] = (i < 256) ? bni[i] : (i < 512 ? bnj[i - 256] : 0.f);
    if (i < 384) g_bE[i] = (i < 256) ? be[i] : bm[i - 256];
    if (i < 16384) {                       // WO [k][n]
        int k = i >> 7, n = i & 127;
        g_WO[i] = Wo[n * 128 + k];
    }
}

// ---------------- HMMA split-bf16 GEMM, 512 threads, N-tile loop ----------------
// mode 0: node tables, NB=5 N-tiles -> g_node_tbl (+bias)
// mode 1: edge pass,  NB=3 N-tiles; nt 0,1 -> attention epilogue; nt 2 -> messages
__global__ void __launch_bounds__(512, 1) mma_kernel(
    int mode, const float* __restrict__ A, int M, int NB,
    const int* __restrict__ EI, const float* __restrict__ AP) {
    extern __shared__ char smem[];
    uint32_t sb = smem_u32(smem);
    int tid = threadIdx.x;
    int wid = tid >> 5, lid = tid & 31;
    int m0 = blockIdx.x * 128;

    const __nv_bfloat16* BhBase = (mode == 0) ? g_WNh : g_WEh;
    const __nv_bfloat16* BlBase = (mode == 0) ? g_WNl : g_WEl;

    // ---- fill A tile once: f32 -> hi/lo bf16 ----
#pragma unroll
    for (int u = tid; u < 4096; u += 512) {
        int r = u >> 5, c = (u & 31) << 2;
        int row = m0 + r;
        float4 v = make_float4(0.f, 0.f, 0.f, 0.f);
        if (row < M) v = *(const float4*)(A + (size_t)row * 128 + c);
        __nv_bfloat162 h01 = __floats2bfloat162_rn(v.x, v.y);
        __nv_bfloat162 h23 = __floats2bfloat162_rn(v.z, v.w);
        float2 f01 = __bfloat1622float2(h01);
        float2 f23 = __bfloat1622float2(h23);
        __nv_bfloat162 l01 = __floats2bfloat162_rn(v.x - f01.x, v.y - f01.y);
        __nv_bfloat162 l23 = __floats2bfloat162_rn(v.z - f23.x, v.w - f23.y);
        uint32_t off = r * APITCH_B + c * 2;
        *(uint2*)(smem + SM_AH + off) = make_uint2(*(uint32_t*)&h01, *(uint32_t*)&h23);
        *(uint2*)(smem + SM_AL + off) = make_uint2(*(uint32_t*)&l01, *(uint32_t*)&l23);
    }
    // ---- fill B tile for nt=0 ----
#pragma unroll
    for (int u = tid; u < 2048; u += 512) {
        int r = u >> 4, c = (u & 15) << 3;
        uint32_t off = r * APITCH_B + c * 2;
        *(uint4*)(smem + SM_BH + off) = *(const uint4*)(BhBase + (size_t)r * 128 + c);
        *(uint4*)(smem + SM_BL + off) = *(const uint4*)(BlBase + (size_t)r * 128 + c);
    }
    __syncthreads();

    // warp tile: 4x4 warp grid, each 32 rows x 32 cols
    int wm = wid & 3, wn = wid >> 2;
    int lr = lid & 15, lc = lid >> 4;

    // epilogue mapping: thread -> row (tid & 127), column quarter (tid >> 7)
    int er = tid & 127, eq = tid >> 7;
    int erow = m0 + er;
    float* Cs = (float*)(smem + SM_C);
    const float* crow = Cs + er * CPITCH + eq * 32;
    int s = 0, dn = 0;
    if (mode == 1) { s = EI[erow]; dn = EI[N_EDGES + erow]; }

    for (int nt = 0; nt < NB; nt++) {
        // ---- MMA over full K=128 ----
        float acc[2][4][4];
#pragma unroll
        for (int i = 0; i < 2; i++)
#pragma unroll
            for (int f = 0; f < 4; f++)
#pragma unroll
                for (int j = 0; j < 4; j++) acc[i][f][j] = 0.f;

#pragma unroll
        for (int ks = 0; ks < 8; ks++) {
            int kc = ks * 16;
            uint32_t ah[2][4], al[2][4], bhf[4][2], blf[4][2];
#pragma unroll
            for (int mf = 0; mf < 2; mf++) {
                uint32_t aoff = (uint32_t)((wm * 32 + mf * 16 + lr) * APITCH_B + (kc + lc * 8) * 2);
                LDSM_X4(ah[mf][0], ah[mf][1], ah[mf][2], ah[mf][3], sb + SM_AH + aoff);
                LDSM_X4(al[mf][0], al[mf][1], al[mf][2], al[mf][3], sb + SM_AL + aoff);
            }
#pragma unroll
            for (int g = 0; g < 2; g++) {
                uint32_t boff = (uint32_t)((wn * 32 + g * 16 + lr) * APITCH_B + (kc + lc * 8) * 2);
                uint32_t t0, t1, t2, t3;
                LDSM_X4(t0, t1, t2, t3, sb + SM_BH + boff);
                bhf[2 * g][0] = t0; bhf[2 * g][1] = t2;
                bhf[2 * g + 1][0] = t1; bhf[2 * g + 1][1] = t3;
                LDSM_X4(t0, t1, t2, t3, sb + SM_BL + boff);
                blf[2 * g][0] = t0; blf[2 * g][1] = t2;
                blf[2 * g + 1][0] = t1; blf[2 * g + 1][1] = t3;
            }
#pragma unroll
            for (int mf = 0; mf < 2; mf++)
#pragma unroll
                for (int f = 0; f < 4; f++) {
                    MMA_BF16(acc[mf][f], ah[mf], bhf[f]);
                    MMA_BF16(acc[mf][f], ah[mf], blf[f]);
                    MMA_BF16(acc[mf][f], al[mf], bhf[f]);
                }
        }

        // ---- stage C (plain layout, pitch 132 floats) ----
#pragma unroll
        for (int mf = 0; mf < 2; mf++)
#pragma unroll
            for (int f = 0; f < 4; f++) {
                int r0 = wm * 32 + mf * 16 + (lid >> 2);
                int cl = wn * 32 + f * 8 + (lid & 3) * 2;
                *(float2*)(Cs + r0 * CPITCH + cl)       = make_float2(acc[mf][f][0], acc[mf][f][1]);
                *(float2*)(Cs + (r0 + 8) * CPITCH + cl) = make_float2(acc[mf][f][2], acc[mf][f][3]);
            }
        __syncthreads();   // C visible; all warps done reading B(nt)

        // ---- prefetch B(nt+1): global loads issue before/under epilogue ----
        if (nt + 1 < NB) {
            const __nv_bfloat16* Bh = BhBase + (size_t)(nt + 1) * 128 * 128;
            const __nv_bfloat16* Bl = BlBase + (size_t)(nt + 1) * 128 * 128;
#pragma unroll
            for (int u = tid; u < 2048; u += 512) {
                int r = u >> 4, c = (u & 15) << 3;
                uint32_t off = r * APITCH_B + c * 2;
                *(uint4*)(smem + SM_BH + off) = *(const uint4*)(Bh + (size_t)r * 128 + c);
                *(uint4*)(smem + SM_BL + off) = *(const uint4*)(Bl + (size_t)r * 128 + c);
            }
        }

        // ---- epilogue for tile nt: thread owns (row er, cols eq*32..+32) ----
        if (mode == 0) {
            if (erow < M) {
                int cb = nt * 128 + eq * 32;
                float* dst = g_node_tbl + (size_t)erow * 640 + cb;
                const float* bi = g_bN + cb;
#pragma unroll
                for (int j = 0; j < 32; j += 4) {
                    float4 c4 = *(const float4*)(crow + j);
                    float4 o;
                    o.x = c4.x + bi[j + 0];
                    o.y = c4.y + bi[j + 1];
                    o.z = c4.z + bi[j + 2];
                    o.w = c4.w + bi[j + 3];
                    *(float4*)(dst + j) = o;
                }
            }
        } else if (nt < 2) {
            int head = nt * 4 + eq;
            int cg = nt * 128 + eq * 32;
            const float* bi = g_bE + cg;
            const float* ap = AP + head * 32;
            const float* ni = g_node_tbl + (size_t)s  * 640 + cg;
            const float* nj = g_node_tbl + (size_t)dn * 640 + 256 + cg;
            float p = 0.f;
#pragma unroll
            for (int j = 0; j < 32; j += 4) {
                float4 c4 = *(const float4*)(crow + j);
                float4 nv = *(const float4*)(ni + j);
                float4 jv = *(const float4*)(nj + j);
                float4 bv = *(const float4*)(bi + j);
                float4 av = *(const float4*)(ap + j);
                float hh;
                hh = c4.x + bv.x + nv.x + jv.x; hh = (hh >= 0.f) ? hh : NEG_SLOPE * hh; p += hh * av.x;
                hh = c4.y + bv.y + nv.y + jv.y; hh = (hh >= 0.f) ? hh : NEG_SLOPE * hh; p += hh * av.y;
                hh = c4.z + bv.z + nv.z + jv.z; hh = (hh >= 0.f) ? hh : NEG_SLOPE * hh; p += hh * av.z;
                hh = c4.w + bv.w + nv.w + jv.w; hh = (hh >= 0.f) ? hh : NEG_SLOPE * hh; p += hh * av.w;
            }
            float ex = expf(p);
            g_ex[erow * 8 + head] = ex;
            atomicAdd(&g_node_sum[s * 8 + head], ex);
        } else {
            const float* nm = g_node_tbl + (size_t)dn * 640 + 512 + eq * 32;
            const float* bi = g_bE + 256 + eq * 32;
            float* dst = g_msg + (size_t)erow * 128 + eq * 32;
#pragma unroll
            for (int j = 0; j < 32; j += 4) {
                float4 c4 = *(const float4*)(crow + j);
                float4 o;
                o.x = c4.x + bi[j + 0] + nm[j + 0];
                o.y = c4.y + bi[j + 1] + nm[j + 1];
                o.z = c4.z + bi[j + 2] + nm[j + 2];
                o.w = c4.w + bi[j + 3] + nm[j + 3];
                *(float4*)(dst + j) = o;
            }
        }
        __syncthreads();   // B(nt+1) filled, C reads done
    }
}

// ---------------- softmax-weight + scatter-aggregate ----------------
__global__ void agg_kernel(const int* __restrict__ EI) {
    int e = (blockIdx.x * blockDim.x + threadIdx.x) >> 5;
    int lane = threadIdx.x & 31;
    if (e >= N_EDGES) return;
    int s = EI[e];
    int head = lane >> 2;
    float ex = g_ex[e * 8 + head];
    float sum = g_node_sum[s * 8 + head];
    float w = ex / sum;
    float4 m = *(const float4*)(g_msg + (size_t)e * 128 + lane * 4);
    float* dst = g_agg + (size_t)s * 128 + lane * 4;
    asm volatile("red.global.add.v4.f32 [%0], {%1,%2,%3,%4};"
                 :: "l"(dst), "f"(m.x * w), "f"(m.y * w), "f"(m.z * w), "f"(m.w * w)
                 : "memory");
}

// ---------------- FFMA GEMM for the small output projection ----------------
__global__ void gemm_kernel(const float* __restrict__ A, const float* __restrict__ B,
                            const float* __restrict__ bias, float* __restrict__ C,
                            int M, int N, int K) {
    __shared__ float As[16][64];
    __shared__ float Bs[16][64];
    int tid = threadIdx.x;
    int rt = tid >> 4, ct = tid & 15;
    int m0 = blockIdx.x * 64, n0 = blockIdx.y * 64;
    float acc[4][4] = {};
    int arow = tid >> 2, aq = tid & 3;
    int bk = tid >> 4, bq = tid & 15;
    for (int k0 = 0; k0 < K; k0 += 16) {
        float4 av = make_float4(0.f, 0.f, 0.f, 0.f);
        if (m0 + arow < M)
            av = *(const float4*)(A + (size_t)(m0 + arow) * K + k0 + aq * 4);
        As[aq * 4 + 0][arow] = av.x; As[aq * 4 + 1][arow] = av.y;
        As[aq * 4 + 2][arow] = av.z; As[aq * 4 + 3][arow] = av.w;
        float4 bv = *(const float4*)(B + (size_t)(k0 + bk) * N + n0 + bq * 4);
        *(float4*)&Bs[bk][bq * 4] = bv;
        __syncthreads();
#pragma unroll
        for (int kk = 0; kk < 16; kk++) {
            float a[4], b[4];
            *(float4*)a = *(float4*)&As[kk][rt * 4];
            *(float4*)b = *(float4*)&Bs[kk][ct * 4];
#pragma unroll
            for (int i = 0; i < 4; i++)
#pragma unroll
                for (int j = 0; j < 4; j++)
                    acc[i][j] += a[i] * b[j];
        }
        __syncthreads();
    }
#pragma unroll
    for (int i = 0; i < 4; i++) {
        int m = m0 + rt * 4 + i;
        if (m < M) {
            int n = n0 + ct * 4;
            float4 o;
            o.x = acc[i][0] + bias[n + 0];
            o.y = acc[i][1] + bias[n + 1];
            o.z = acc[i][2] + bias[n + 2];
            o.w = acc[i][3] + bias[n + 3];
            *(float4*)(C + (size_t)m * N + n) = o;
        }
    }
}

// ---------------- launch ----------------
extern "C" void kernel_launch(void* const* d_in, const int* in_sizes, int n_in,
                              void* d_out, int out_size) {
    const float* node_features = (const float*)d_in[0];
    const float* edge_features = (const float*)d_in[1];
    const int*   edge_index    = (const int*)d_in[2];
    const float* Wni = (const float*)d_in[3];
    const float* bni = (const float*)d_in[4];
    const float* Wnj = (const float*)d_in[5];
    const float* bnj = (const float*)d_in[6];
    const float* We  = (const float*)d_in[7];
    const float* be  = (const float*)d_in[8];
    const float* attn_proj = (const float*)d_in[9];
    const float* Wm  = (const float*)d_in[10];
    const float* bm  = (const float*)d_in[11];
    const float* Wo  = (const float*)d_in[12];
    const float* bo  = (const float*)d_in[13];
    float* out = (float*)d_out;

    float *pAgg, *pWO;
    cudaGetSymbolAddress((void**)&pAgg, g_agg);
    cudaGetSymbolAddress((void**)&pWO,  g_WO);

    static bool attr_set = false;
    if (!attr_set) {
        cudaFuncSetAttribute(mma_kernel, cudaFuncAttributeMaxDynamicSharedMemorySize, SM_TOT);
        attr_set = true;
    }

    const int ZTOT = N_NODES * NUM_HEADS + N_NODES * 128;
    zero_kernel<<<(ZTOT + 255) / 256, 256>>>();
    prepack_kernel<<<(81920 + 255) / 256, 256>>>(Wni, bni, Wnj, bnj, We, be, Wm, bm, Wo);

    // node tables: 157 M-tiles, 5 N-tiles looped in-kernel
    mma_kernel<<<(N_NODES + 127) / 128, 512, SM_TOT>>>(
        0, node_features, N_NODES, 5, edge_index, attn_proj);

    // edge pass: 2500 M-tiles, 3 N-tiles looped in-kernel
    mma_kernel<<<N_EDGES / 128, 512, SM_TOT>>>(
        1, edge_features, N_EDGES, 3, edge_index, attn_proj);

    // aggregate: one warp per edge
    agg_kernel<<<N_EDGES / 8, 256>>>(edge_index);

    // output projection
    gemm_kernel<<<dim3((N_NODES + 63) / 64, 2), 256>>>(pAgg, pWO, bo, out, N_NODES, 128, 128);
}

// round 7
// speedup vs baseline: 2.1137x; 1.7635x over previous
#include <cuda_runtime.h>
#include <cuda_bf16.h>
#include <cstdint>

#define N_NODES   20000
#define N_EDGES   320000
#define NUM_HEADS 8
#define NEG_SLOPE 0.2f

// ---------------- device scratch ----------------
__device__ float g_node_tbl[N_NODES * 640];   // [0:256)=ni_h, [256:512)=nj_h, [512:640)=node msg part
__device__ float g_ex[N_EDGES * NUM_HEADS];
__device__ float g_msg[N_EDGES * 128];
__device__ float g_node_sum[N_NODES * NUM_HEADS];
__device__ float g_agg[N_NODES * 128];
// prepacked weights (bf16 hi/lo splits, [n][k] k-contiguous == col-major B for mma)
__device__ __nv_bfloat16 g_WNh[640 * 128];
__device__ __nv_bfloat16 g_WNl[640 * 128];
__device__ __nv_bfloat16 g_WEh[384 * 128];
__device__ __nv_bfloat16 g_WEl[384 * 128];
__device__ float g_bN[640];
__device__ float g_bE[384];
__device__ float g_WO[128 * 128];             // [k][n] for FFMA out gemm

// ---------------- helpers ----------------
__device__ __forceinline__ uint32_t smem_u32(const void* p) {
    uint32_t a;
    asm("{ .reg .u64 t; cvta.to.shared.u64 t, %1; cvt.u32.u64 %0, t; }" : "=r"(a) : "l"(p));
    return a;
}

#define LDSM_X4(r0, r1, r2, r3, addr) \
    asm volatile("ldmatrix.sync.aligned.m8n8.x4.shared.b16 {%0,%1,%2,%3}, [%4];" \
                 : "=r"(r0), "=r"(r1), "=r"(r2), "=r"(r3) : "r"(addr))

#define MMA_BF16(c, a, b) \
    asm volatile("mma.sync.aligned.m16n8k16.row.col.f32.bf16.bf16.f32 " \
                 "{%0,%1,%2,%3}, {%4,%5,%6,%7}, {%8,%9}, {%0,%1,%2,%3};" \
                 : "+f"((c)[0]), "+f"((c)[1]), "+f"((c)[2]), "+f"((c)[3]) \
                 : "r"((a)[0]), "r"((a)[1]), "r"((a)[2]), "r"((a)[3]), \
                   "r"((b)[0]), "r"((b)[1]))

// smem layout (bytes): A hi/lo 128x128 bf16 (pitch 272 B), B hi/lo 64x128 bf16
#define APITCH_B 272
#define SM_AH 0
#define SM_AL 34816
#define SM_BH 69632
#define SM_BL 87040
#define SM_TOT 104448     // <= 113 KB -> 2 CTAs/SM

// ---------------- init kernels ----------------
__global__ void zero_kernel() {
    int i = blockIdx.x * blockDim.x + threadIdx.x;
    const int NS = N_NODES * NUM_HEADS;
    const int TOT = NS + N_NODES * 128;
    if (i < NS) g_node_sum[i] = 0.f;
    else if (i < TOT) g_agg[i - NS] = 0.f;
}

__device__ __forceinline__ void split_store(float v, __nv_bfloat16* hi, __nv_bfloat16* lo, int i) {
    __nv_bfloat16 h = __float2bfloat16(v);
    hi[i] = h;
    lo[i] = __float2bfloat16(v - __bfloat162float(h));
}

__global__ void prepack_kernel(const float* __restrict__ Wni, const float* __restrict__ bni,
                               const float* __restrict__ Wnj, const float* __restrict__ bnj,
                               const float* __restrict__ We,  const float* __restrict__ be,
                               const float* __restrict__ Wm,  const float* __restrict__ bm,
                               const float* __restrict__ Wo) {
    int i = blockIdx.x * blockDim.x + threadIdx.x;
    if (i < 81920) {                       // WN [640][128]
        int n = i >> 7, k = i & 127;
        float v;
        if (n < 256)      v = Wni[n * 128 + k];
        else if (n < 512) v = Wnj[(n - 256) * 128 + k];
        else              v = Wm[(n - 512) * 256 + k];
        split_store(v, g_WNh, g_WNl, i);
    }
    if (i < 49152) {                       // WE [384][128]
        int n = i >> 7, k = i & 127;
        float v = (n < 256) ? We[n * 128 + k] : Wm[(n - 256) * 256 + 128 + k];
        split_store(v, g_WEh, g_WEl, i);
    }
    if (i < 640) g_bN[i] = (i < 256) ? bni[i] : (i < 512 ? bnj[i - 256] : 0.f);
    if (i < 384) g_bE[i] = (i < 256) ? be[i] : bm[i - 256];
    if (i < 16384) {                       // WO [k][n]
        int k = i >> 7, n = i & 127;
        g_WO[i] = Wo[n * 128 + k];
    }
}

// ---------------- HMMA split-bf16 GEMM, register epilogue, 2 CTAs/SM ----------------
// 512 threads = 16 warps: wm = wid>>1 (16-row strip), wn = wid&1 (32-col half of 64-wide N-tile)
// mode 0: node tables, NB=10 -> g_node_tbl (+bias)
// mode 1: edge pass,  NB=6; nt 0..3 -> attention epilogue (head = nt*2+wn); nt 4,5 -> messages
__global__ void __launch_bounds__(512, 2) mma_kernel(
    int mode, const float* __restrict__ A, int M, int NB,
    const int* __restrict__ EI, const float* __restrict__ AP) {
    extern __shared__ char smem[];
    uint32_t sb = smem_u32(smem);
    int tid = threadIdx.x;
    int wid = tid >> 5, lid = tid & 31;
    int m0 = blockIdx.x * 128;

    const __nv_bfloat16* BhBase = (mode == 0) ? g_WNh : g_WEh;
    const __nv_bfloat16* BlBase = (mode == 0) ? g_WNl : g_WEl;

    // ---- fill A tile once: f32 -> hi/lo bf16 ----
#pragma unroll
    for (int u = tid; u < 4096; u += 512) {
        int r = u >> 5, c = (u & 31) << 2;
        int row = m0 + r;
        float4 v = make_float4(0.f, 0.f, 0.f, 0.f);
        if (row < M) v = *(const float4*)(A + (size_t)row * 128 + c);
        __nv_bfloat162 h01 = __floats2bfloat162_rn(v.x, v.y);
        __nv_bfloat162 h23 = __floats2bfloat162_rn(v.z, v.w);
        float2 f01 = __bfloat1622float2(h01);
        float2 f23 = __bfloat1622float2(h23);
        __nv_bfloat162 l01 = __floats2bfloat162_rn(v.x - f01.x, v.y - f01.y);
        __nv_bfloat162 l23 = __floats2bfloat162_rn(v.z - f23.x, v.w - f23.y);
        uint32_t off = r * APITCH_B + c * 2;
        *(uint2*)(smem + SM_AH + off) = make_uint2(*(uint32_t*)&h01, *(uint32_t*)&h23);
        *(uint2*)(smem + SM_AL + off) = make_uint2(*(uint32_t*)&l01, *(uint32_t*)&l23);
    }

    int wm = wid >> 1, wn = wid & 1;
    int lr = lid & 15, lc = lid >> 4;
    int q  = lid >> 2, lq = lid & 3;          // C-frag: rows wm*16+q, +8; cols 2*lq within 8-col frag

    // per-lane edge/node rows (fixed across tiles)
    int r0 = m0 + wm * 16 + q;
    int r1 = r0 + 8;
    int s0 = 0, d0 = 0, s1 = 0, d1 = 0;
    if (mode == 1) {
        s0 = EI[r0]; d0 = EI[N_EDGES + r0];
        s1 = EI[r1]; d1 = EI[N_EDGES + r1];
    }

    for (int nt = 0; nt < NB; nt++) {
        __syncthreads();   // previous tile's ldsm done (A ready on first iter)
        // ---- fill B(nt): 64 rows x 128 cols hi/lo ----
        {
            const __nv_bfloat16* Bh = BhBase + (size_t)nt * 64 * 128;
            const __nv_bfloat16* Bl = BlBase + (size_t)nt * 64 * 128;
#pragma unroll
            for (int u = tid; u < 1024; u += 512) {
                int r = u >> 4, c = (u & 15) << 3;
                uint32_t off = r * APITCH_B + c * 2;
                *(uint4*)(smem + SM_BH + off) = *(const uint4*)(Bh + (size_t)r * 128 + c);
                *(uint4*)(smem + SM_BL + off) = *(const uint4*)(Bl + (size_t)r * 128 + c);
            }
        }
        __syncthreads();

        // ---- MMA over K=128: warp tile 16 rows x 32 cols ----
        float acc[4][4];
#pragma unroll
        for (int f = 0; f < 4; f++)
#pragma unroll
            for (int j = 0; j < 4; j++) acc[f][j] = 0.f;

#pragma unroll
        for (int ks = 0; ks < 8; ks++) {
            int kc = ks * 16;
            uint32_t ah[4], al[4], bhf[4][2], blf[4][2];
            uint32_t aoff = (uint32_t)((wm * 16 + lr) * APITCH_B + (kc + lc * 8) * 2);
            LDSM_X4(ah[0], ah[1], ah[2], ah[3], sb + SM_AH + aoff);
            LDSM_X4(al[0], al[1], al[2], al[3], sb + SM_AL + aoff);
#pragma unroll
            for (int g = 0; g < 2; g++) {
                uint32_t boff = (uint32_t)((wn * 32 + g * 16 + lr) * APITCH_B + (kc + lc * 8) * 2);
                uint32_t t0, t1, t2, t3;
                LDSM_X4(t0, t1, t2, t3, sb + SM_BH + boff);
                bhf[2 * g][0] = t0; bhf[2 * g][1] = t2;
                bhf[2 * g + 1][0] = t1; bhf[2 * g + 1][1] = t3;
                LDSM_X4(t0, t1, t2, t3, sb + SM_BL + boff);
                blf[2 * g][0] = t0; blf[2 * g][1] = t2;
                blf[2 * g + 1][0] = t1; blf[2 * g + 1][1] = t3;
            }
#pragma unroll
            for (int f = 0; f < 4; f++) {
                MMA_BF16(acc[f], ah, bhf[f]);
                MMA_BF16(acc[f], ah, blf[f]);
                MMA_BF16(acc[f], al, bhf[f]);
            }
        }

        // ---- register epilogue ----
        if (mode == 0) {
            int cg0 = nt * 64 + wn * 32;
#pragma unroll
            for (int f = 0; f < 4; f++) {
                int cg = cg0 + f * 8 + lq * 2;
                float2 b2 = *(const float2*)(g_bN + cg);
                if (r0 < M)
                    *(float2*)(g_node_tbl + (size_t)r0 * 640 + cg) =
                        make_float2(acc[f][0] + b2.x, acc[f][1] + b2.y);
                if (r1 < M)
                    *(float2*)(g_node_tbl + (size_t)r1 * 640 + cg) =
                        make_float2(acc[f][2] + b2.x, acc[f][3] + b2.y);
            }
        } else if (nt < 4) {
            int head = nt * 2 + wn;
            int cg0 = nt * 64 + wn * 32;          // hidden col base (0..224)
            float p0 = 0.f, p1 = 0.f;
#pragma unroll
            for (int f = 0; f < 4; f++) {
                int cl = f * 8 + lq * 2;          // col within head (0..30)
                int cg = cg0 + cl;
                float2 b2  = *(const float2*)(g_bE + cg);
                float2 ap2 = *(const float2*)(AP + head * 32 + cl);
                float2 ni0 = *(const float2*)(g_node_tbl + (size_t)s0 * 640 + cg);
                float2 nj0 = *(const float2*)(g_node_tbl + (size_t)d0 * 640 + 256 + cg);
                float2 ni1 = *(const float2*)(g_node_tbl + (size_t)s1 * 640 + cg);
                float2 nj1 = *(const float2*)(g_node_tbl + (size_t)d1 * 640 + 256 + cg);
                float h;
                h = acc[f][0] + b2.x + ni0.x + nj0.x; h = (h >= 0.f) ? h : NEG_SLOPE * h; p0 += h * ap2.x;
                h = acc[f][1] + b2.y + ni0.y + nj0.y; h = (h >= 0.f) ? h : NEG_SLOPE * h; p0 += h * ap2.y;
                h = acc[f][2] + b2.x + ni1.x + nj1.x; h = (h >= 0.f) ? h : NEG_SLOPE * h; p1 += h * ap2.x;
                h = acc[f][3] + b2.y + ni1.y + nj1.y; h = (h >= 0.f) ? h : NEG_SLOPE * h; p1 += h * ap2.y;
            }
            p0 += __shfl_xor_sync(0xffffffffu, p0, 1);
            p0 += __shfl_xor_sync(0xffffffffu, p0, 2);
            p1 += __shfl_xor_sync(0xffffffffu, p1, 1);
            p1 += __shfl_xor_sync(0xffffffffu, p1, 2);
            if (lq == 0) {
                float e0 = expf(p0), e1 = expf(p1);
                g_ex[r0 * 8 + head] = e0;
                g_ex[r1 * 8 + head] = e1;
                atomicAdd(&g_node_sum[s0 * 8 + head], e0);
                atomicAdd(&g_node_sum[s1 * 8 + head], e1);
            }
        } else {
            int cm0 = (nt - 4) * 64 + wn * 32;    // message col base (0..96)
#pragma unroll
            for (int f = 0; f < 4; f++) {
                int cm = cm0 + f * 8 + lq * 2;
                float2 b2  = *(const float2*)(g_bE + 256 + cm);
                float2 nm0 = *(const float2*)(g_node_tbl + (size_t)d0 * 640 + 512 + cm);
                float2 nm1 = *(const float2*)(g_node_tbl + (size_t)d1 * 640 + 512 + cm);
                *(float2*)(g_msg + (size_t)r0 * 128 + cm) =
                    make_float2(acc[f][0] + b2.x + nm0.x, acc[f][1] + b2.y + nm0.y);
                *(float2*)(g_msg + (size_t)r1 * 128 + cm) =
                    make_float2(acc[f][2] + b2.x + nm1.x, acc[f][3] + b2.y + nm1.y);
            }
        }
    }
}

// ---------------- softmax-weight + scatter-aggregate ----------------
__global__ void agg_kernel(const int* __restrict__ EI) {
    int e = (blockIdx.x * blockDim.x + threadIdx.x) >> 5;
    int lane = threadIdx.x & 31;
    if (e >= N_EDGES) return;
    int s = EI[e];
    int head = lane >> 2;
    float ex = g_ex[e * 8 + head];
    float sum = g_node_sum[s * 8 + head];
    float w = ex / sum;
    float4 m = *(const float4*)(g_msg + (size_t)e * 128 + lane * 4);
    float* dst = g_agg + (size_t)s * 128 + lane * 4;
    asm volatile("red.global.add.v4.f32 [%0], {%1,%2,%3,%4};"
                 :: "l"(dst), "f"(m.x * w), "f"(m.y * w), "f"(m.z * w), "f"(m.w * w)
                 : "memory");
}

// ---------------- FFMA GEMM for the small output projection ----------------
__global__ void gemm_kernel(const float* __restrict__ A, const float* __restrict__ B,
                            const float* __restrict__ bias, float* __restrict__ C,
                            int M, int N, int K) {
    __shared__ float As[16][64];
    __shared__ float Bs[16][64];
    int tid = threadIdx.x;
    int rt = tid >> 4, ct = tid & 15;
    int m0 = blockIdx.x * 64, n0 = blockIdx.y * 64;
    float acc[4][4] = {};
    int arow = tid >> 2, aq = tid & 3;
    int bk = tid >> 4, bq = tid & 15;
    for (int k0 = 0; k0 < K; k0 += 16) {
        float4 av = make_float4(0.f, 0.f, 0.f, 0.f);
        if (m0 + arow < M)
            av = *(const float4*)(A + (size_t)(m0 + arow) * K + k0 + aq * 4);
        As[aq * 4 + 0][arow] = av.x; As[aq * 4 + 1][arow] = av.y;
        As[aq * 4 + 2][arow] = av.z; As[aq * 4 + 3][arow] = av.w;
        float4 bv = *(const float4*)(B + (size_t)(k0 + bk) * N + n0 + bq * 4);
        *(float4*)&Bs[bk][bq * 4] = bv;
        __syncthreads();
#pragma unroll
        for (int kk = 0; kk < 16; kk++) {
            float a[4], b[4];
            *(float4*)a = *(float4*)&As[kk][rt * 4];
            *(float4*)b = *(float4*)&Bs[kk][ct * 4];
#pragma unroll
            for (int i = 0; i < 4; i++)
#pragma unroll
                for (int j = 0; j < 4; j++)
                    acc[i][j] += a[i] * b[j];
        }
        __syncthreads();
    }
#pragma unroll
    for (int i = 0; i < 4; i++) {
        int m = m0 + rt * 4 + i;
        if (m < M) {
            int n = n0 + ct * 4;
            float4 o;
            o.x = acc[i][0] + bias[n + 0];
            o.y = acc[i][1] + bias[n + 1];
            o.z = acc[i][2] + bias[n + 2];
            o.w = acc[i][3] + bias[n + 3];
            *(float4*)(C + (size_t)m * N + n) = o;
        }
    }
}

// ---------------- launch ----------------
extern "C" void kernel_launch(void* const* d_in, const int* in_sizes, int n_in,
                              void* d_out, int out_size) {
    const float* node_features = (const float*)d_in[0];
    const float* edge_features = (const float*)d_in[1];
    const int*   edge_index    = (const int*)d_in[2];
    const float* Wni = (const float*)d_in[3];
    const float* bni = (const float*)d_in[4];
    const float* Wnj = (const float*)d_in[5];
    const float* bnj = (const float*)d_in[6];
    const float* We  = (const float*)d_in[7];
    const float* be  = (const float*)d_in[8];
    const float* attn_proj = (const float*)d_in[9];
    const float* Wm  = (const float*)d_in[10];
    const float* bm  = (const float*)d_in[11];
    const float* Wo  = (const float*)d_in[12];
    const float* bo  = (const float*)d_in[13];
    float* out = (float*)d_out;

    float *pAgg, *pWO;
    cudaGetSymbolAddress((void**)&pAgg, g_agg);
    cudaGetSymbolAddress((void**)&pWO,  g_WO);

    static bool attr_set = false;
    if (!attr_set) {
        cudaFuncSetAttribute(mma_kernel, cudaFuncAttributeMaxDynamicSharedMemorySize, SM_TOT);
        attr_set = true;
    }

    const int ZTOT = N_NODES * NUM_HEADS + N_NODES * 128;
    zero_kernel<<<(ZTOT + 255) / 256, 256>>>();
    prepack_kernel<<<(81920 + 255) / 256, 256>>>(Wni, bni, Wnj, bnj, We, be, Wm, bm, Wo);

    // node tables: 157 M-tiles, 10 N-tiles of 64 looped in-kernel
    mma_kernel<<<(N_NODES + 127) / 128, 512, SM_TOT>>>(
        0, node_features, N_NODES, 10, edge_index, attn_proj);

    // edge pass: 2500 M-tiles, 6 N-tiles of 64 looped in-kernel
    mma_kernel<<<N_EDGES / 128, 512, SM_TOT>>>(
        1, edge_features, N_EDGES, 6, edge_index, attn_proj);

    // aggregate: one warp per edge
    agg_kernel<<<N_EDGES / 8, 256>>>(edge_index);

    // output projection
    gemm_kernel<<<dim3((N_NODES + 63) / 64, 2), 256>>>(pAgg, pWO, bo, out, N_NODES, 128, 128);
}